// round 2
// baseline (speedup 1.0000x reference)
#include <cuda_runtime.h>
#include <cuda_bf16.h>

#define TOKENS_PER_BLOCK 64
#define KC 32
#define NEXP 64
#define DMODEL 4096

// Fused router: logits GEMM (x@W+b) + softmax(64) + top-2 + renorm.
// Block: 256 threads = 16x16 grid. Thread (ty,tx) computes a 4-token x 4-expert
// microtile. Token t's 64 experts live in 16 consecutive lanes (tx=0..15),
// so softmax/top-2 reductions are width-16 warp shuffles.
__global__ __launch_bounds__(256, 4) void router_kernel(
    const float* __restrict__ x, const float* __restrict__ W,
    const float* __restrict__ b,
    float* __restrict__ probs_out, float* __restrict__ tkp_out,
    float* __restrict__ tki_out)
{
    __shared__ float xs[TOKENS_PER_BLOCK][KC];   // 64 x 32 fp32 = 8 KB
    __shared__ float ws[KC][NEXP];               // 32 x 64 fp32 = 8 KB

    const int tid = threadIdx.x;
    const int tx = tid & 15;        // expert-group 0..15 (4 experts each)
    const int ty = tid >> 4;        // token-group  0..15 (4 tokens each)
    const int tok0 = blockIdx.x * TOKENS_PER_BLOCK;

    float acc[4][4];
    #pragma unroll
    for (int i = 0; i < 4; i++)
        #pragma unroll
        for (int j = 0; j < 4; j++) acc[i][j] = 0.f;

    for (int k0 = 0; k0 < DMODEL; k0 += KC) {
        // ---- load x tile: 64 tokens x 32 k = 512 float4, 2 per thread ----
        #pragma unroll
        for (int r = 0; r < 2; r++) {
            int f4 = tid + r * 256;          // 0..511
            int t  = f4 >> 3;                // 8 float4 per 32-wide row
            int c  = (f4 & 7) * 4;
            float4 v = *reinterpret_cast<const float4*>(
                &x[(size_t)(tok0 + t) * DMODEL + k0 + c]);
            *reinterpret_cast<float4*>(&xs[t][c]) = v;
        }
        // ---- load W tile: rows k0..k0+31 x 64 experts = 512 float4 ----
        #pragma unroll
        for (int r = 0; r < 2; r++) {
            int f4 = tid + r * 256;
            int kk = f4 >> 4;                // 16 float4 per 64-wide row
            int c  = (f4 & 15) * 4;
            float4 v = *reinterpret_cast<const float4*>(
                &W[(size_t)(k0 + kk) * NEXP + c]);
            *reinterpret_cast<float4*>(&ws[kk][c]) = v;
        }
        __syncthreads();

        #pragma unroll
        for (int kk = 0; kk < KC; kk++) {
            float4 w4 = *reinterpret_cast<const float4*>(&ws[kk][tx * 4]);
            float wv[4] = {w4.x, w4.y, w4.z, w4.w};
            float xv[4];
            #pragma unroll
            for (int i = 0; i < 4; i++) xv[i] = xs[ty * 4 + i][kk];
            #pragma unroll
            for (int i = 0; i < 4; i++)
                #pragma unroll
                for (int j = 0; j < 4; j++)
                    acc[i][j] = fmaf(xv[i], wv[j], acc[i][j]);
        }
        __syncthreads();
    }

    // ---- bias ----
    float4 b4 = *reinterpret_cast<const float4*>(&b[tx * 4]);
    const float bias[4] = {b4.x, b4.y, b4.z, b4.w};

    const unsigned mask = 0xffffffffu;

    #pragma unroll
    for (int i = 0; i < 4; i++) {
        const int token = tok0 + ty * 4 + i;
        float v[4];
        #pragma unroll
        for (int j = 0; j < 4; j++) v[j] = acc[i][j] + bias[j];

        // softmax over 64 = 4 local + width-16 shuffle reduce
        float m = fmaxf(fmaxf(v[0], v[1]), fmaxf(v[2], v[3]));
        #pragma unroll
        for (int s = 8; s >= 1; s >>= 1)
            m = fmaxf(m, __shfl_xor_sync(mask, m, s, 16));

        float e[4];
        float sum = 0.f;
        #pragma unroll
        for (int j = 0; j < 4; j++) { e[j] = __expf(v[j] - m); sum += e[j]; }
        #pragma unroll
        for (int s = 8; s >= 1; s >>= 1)
            sum += __shfl_xor_sync(mask, sum, s, 16);

        const float inv = 1.f / sum;
        float p[4];
        #pragma unroll
        for (int j = 0; j < 4; j++) p[j] = e[j] * inv;

        *reinterpret_cast<float4*>(&probs_out[(size_t)token * NEXP + tx * 4]) =
            make_float4(p[0], p[1], p[2], p[3]);

        // local top-2 of 4
        float p1 = -1.f, p2 = -1.f;
        int e1 = 0, e2 = 0;
        #pragma unroll
        for (int j = 0; j < 4; j++) {
            float pv = p[j];
            int ei = tx * 4 + j;
            if (pv > p1) { p2 = p1; e2 = e1; p1 = pv; e1 = ei; }
            else if (pv > p2) { p2 = pv; e2 = ei; }
        }
        // merge across 16 lanes
        #pragma unroll
        for (int s = 1; s < 16; s <<= 1) {
            float op1 = __shfl_xor_sync(mask, p1, s, 16);
            int   oe1 = __shfl_xor_sync(mask, e1, s, 16);
            float op2 = __shfl_xor_sync(mask, p2, s, 16);
            int   oe2 = __shfl_xor_sync(mask, e2, s, 16);
            if (op1 > p1) {
                if (p1 > op2) { p2 = p1; e2 = e1; }
                else          { p2 = op2; e2 = oe2; }
                p1 = op1; e1 = oe1;
            } else if (op1 > p2) {
                p2 = op1; e2 = oe1;
            }
        }

        if (tx == 0) {
            float is2 = 1.f / (p1 + p2 + 1e-9f);
            tkp_out[(size_t)token * 2]     = p1 * is2;
            tkp_out[(size_t)token * 2 + 1] = p2 * is2;
            tki_out[(size_t)token * 2]     = (float)e1;
            tki_out[(size_t)token * 2 + 1] = (float)e2;
        }
    }
}

extern "C" void kernel_launch(void* const* d_in, const int* in_sizes, int n_in,
                              void* d_out, int out_size) {
    const float* x = (const float*)d_in[0];   // [4,4096,4096]
    const float* W = (const float*)d_in[1];   // [4096,64]
    const float* b = (const float*)d_in[2];   // [64]

    const int n_tokens = in_sizes[0] / DMODEL;        // 16384
    float* probs = (float*)d_out;                     // n_tokens*64
    float* tkp   = probs + (size_t)n_tokens * NEXP;   // n_tokens*2
    float* tki   = tkp + (size_t)n_tokens * 2;        // n_tokens*2

    dim3 grid(n_tokens / TOKENS_PER_BLOCK);           // 256 blocks
    router_kernel<<<grid, 256>>>(x, W, b, probs, tkp, tki);
}